// round 7
// baseline (speedup 1.0000x reference)
#include <cuda_runtime.h>
#include <cuda_fp16.h>
#include <stdint.h>

// Problem constants
#define SDIM 4096
#define ADIM 1024
#define DDIM 5
#define HDIM 64

// ---------------- low-level helpers ----------------

__device__ __forceinline__ float tanh_f32(float x) {
    float y;
    asm("tanh.approx.f32 %0, %1;" : "=f"(y) : "f"(x));
    return y;
}

__device__ __forceinline__ unsigned tanh_f16x2(unsigned x) {
    unsigned y;
    asm("tanh.approx.f16x2 %0, %1;" : "=r"(y) : "r"(x));
    return y;
}

// pack: result.lo = lo_val, result.hi = hi_val  (cvt.rn.f16x2.f32 d,a,b -> d.hi=a, d.lo=b)
__device__ __forceinline__ unsigned pack_f16x2(float hi_val, float lo_val) {
    unsigned d;
    asm("cvt.rn.f16x2.f32 %0, %1, %2;" : "=r"(d) : "f"(hi_val), "f"(lo_val));
    return d;
}

__device__ __forceinline__ unsigned pack_halves(__half lo, __half hi) {
    return ((unsigned)__half_as_ushort(hi) << 16) | (unsigned)__half_as_ushort(lo);
}

// fp16 two-term split of (x0,x1): hi = rn(x), lo = rn(x - f32(hi)); packed k-order (x0 in low half)
__device__ __forceinline__ void split2(float x0, float x1, unsigned& hi, unsigned& lo) {
    __half h0 = __float2half_rn(x0);
    __half h1 = __float2half_rn(x1);
    float r0 = x0 - __half2float(h0);
    float r1 = x1 - __half2float(h1);
    hi = pack_halves(h0, h1);
    lo = pack_halves(__float2half_rn(r0), __float2half_rn(r1));
}

__device__ __forceinline__ void mma16(float& c0, float& c1, float& c2, float& c3,
                                      unsigned a0, unsigned a1, unsigned a2, unsigned a3,
                                      unsigned b0, unsigned b1) {
    asm("mma.sync.aligned.m16n8k16.row.col.f32.f16.f16.f32 "
        "{%0,%1,%2,%3},{%4,%5,%6,%7},{%8,%9},{%0,%1,%2,%3};"
        : "+f"(c0), "+f"(c1), "+f"(c2), "+f"(c3)
        : "r"(a0), "r"(a1), "r"(a2), "r"(a3), "r"(b0), "r"(b1));
}

__device__ __forceinline__ void mma8(float& c0, float& c1, float& c2, float& c3,
                                     unsigned a0, unsigned a1, unsigned b0) {
    asm("mma.sync.aligned.m16n8k8.row.col.f32.f16.f16.f32 "
        "{%0,%1,%2,%3},{%4,%5},{%6},{%0,%1,%2,%3};"
        : "+f"(c0), "+f"(c1), "+f"(c2), "+f"(c3)
        : "r"(a0), "r"(a1), "r"(b0));
}

// ---------------- kernel ----------------
// Grid: (ADIM, 8). Block: 256 threads (8 warps), 2 blocks/SM.
// Block (a, y) handles atom a, rows [y*512, y*512+512).
// Each warp processes 32 rows per iteration (2 row-tiles of 16), 2 iterations.

__global__ __launch_bounds__(256, 2)
void nn_grouped_mlp_kernel(const float* __restrict__ g,
                           const float* __restrict__ W1,
                           const float* __restrict__ b1,
                           const float* __restrict__ W2,
                           const float* __restrict__ b2,
                           const float* __restrict__ W3,
                           const float* __restrict__ b3,
                           float* __restrict__ out) {
    // smem: pre-swizzled B-fragments (fp16 hi/lo split) + biases
    __shared__ uint4 w2f[1024];  // [kstep(4)][ntile(8)][lane(32)] : {hi_b0,hi_b1,lo_b0,lo_b1}  16 KB
    __shared__ uint2 w1f[256];   // [ntile(8)][lane(32)]           : {hi_b0, lo_b0}             2 KB
    __shared__ uint4 w3f[128];   // [kstep(4)][lane(32)]           : {hi_b0,hi_b1,lo_b0,lo_b1}  2 KB
    __shared__ float b1s[HDIM];
    __shared__ float b2s[HDIM];

    const int a    = blockIdx.x;
    const int tid  = threadIdx.x;
    const int lane = tid & 31;
    const int warp = tid >> 5;
    const int kp   = lane & 3;   // k-pair index within fragments
    const int row8 = lane >> 2;  // row within 8-row group / n-col selector

    // ---- preprocess W2 into split B-fragments ----
    {
        const float* W2a = W2 + a * (HDIM * HDIM);
        #pragma unroll
        for (int c = tid; c < 1024; c += 256) {
            int l    = c & 31;
            int lkp  = l & 3;
            int colg = (((c >> 5) & 7) << 3) + (l >> 2);  // 8*ntile + lane/4
            int k0   = ((c >> 8) << 4) + (lkp << 1);      // 16*kstep + 2*kp
            float f0 = W2a[(k0    ) * HDIM + colg];
            float f1 = W2a[(k0 + 1) * HDIM + colg];
            float f2 = W2a[(k0 + 8) * HDIM + colg];
            float f3 = W2a[(k0 + 9) * HDIM + colg];
            uint4 q;
            split2(f0, f1, q.x, q.z);
            split2(f2, f3, q.y, q.w);
            w2f[c] = q;
        }
    }
    // ---- preprocess W1 (K padded 5 -> 8) ----
    if (tid < 256) {
        const float* W1a = W1 + a * (DDIM * HDIM);
        int l    = tid & 31;
        int lkp  = l & 3;
        int colg = ((tid >> 5) << 3) + (l >> 2);
        int k0 = 2 * lkp, k1 = 2 * lkp + 1;
        float f0 = (k0 < DDIM) ? W1a[k0 * HDIM + colg] : 0.0f;
        float f1 = (k1 < DDIM) ? W1a[k1 * HDIM + colg] : 0.0f;
        uint2 q;
        split2(f0, f1, q.x, q.y);
        w1f[tid] = q;
    }
    // ---- preprocess W3 (n=8 tile, only col 0 real) ----
    if (tid < 128) {
        const float* W3a = W3 + a * HDIM;
        int l    = tid & 31;
        int lkp  = l & 3;
        int colg = l >> 2;
        int k0   = ((tid >> 5) << 4) + (lkp << 1);
        float f0 = 0.f, f1 = 0.f, f2 = 0.f, f3 = 0.f;
        if (colg == 0) {
            f0 = W3a[k0];
            f1 = W3a[k0 + 1];
            f2 = W3a[k0 + 8];
            f3 = W3a[k0 + 9];
        }
        uint4 q;
        split2(f0, f1, q.x, q.z);
        split2(f2, f3, q.y, q.w);
        w3f[tid] = q;
    }
    // ---- biases into smem (frees 32 registers vs per-thread copies) ----
    if (tid < HDIM) {
        b1s[tid] = b1[a * HDIM + tid];
        b2s[tid] = b2[a * HDIM + tid];
    }
    const float b3v = b3[a];

    __syncthreads();

    const int sbase = blockIdx.y * 512;
    const int kp2   = kp << 1;

    #pragma unroll
    for (int it = 0; it < 2; ++it) {
        const int sb = sbase + it * 256 + warp * 32;  // first row of this warp's 32-row chunk

        // ================= Phase A: GEMM1 (split fp16 MMA) + tanh(f32) + pack h1 ============
        // h1p[rt][4*ks + {0..3}] are directly the GEMM2 A-fragment registers.
        unsigned h1p[2][16];
        #pragma unroll
        for (int rt = 0; rt < 2; ++rt) {
            const int r0 = sb + rt * 16 + row8;  // rows r0 and r0+8
            const float* g0 = g + ((size_t)r0 * ADIM + a) * DDIM;
            const float* g1 = g0 + (size_t)8 * ADIM * DDIM;
            const int k0 = kp2, k1 = kp2 + 1;
            float x00 = (k0 < DDIM) ? g0[k0] : 0.0f;
            float x01 = (k1 < DDIM) ? g0[k1] : 0.0f;
            float x10 = (k0 < DDIM) ? g1[k0] : 0.0f;
            float x11 = (k1 < DDIM) ? g1[k1] : 0.0f;
            unsigned ah0, al0, ah1, al1;
            split2(x00, x01, ah0, al0);
            split2(x10, x11, ah1, al1);

            #pragma unroll
            for (int n = 0; n < 8; ++n) {
                uint2 wb = w1f[n * 32 + lane];
                float c0 = b1s[(n << 3) + kp2];
                float c1 = b1s[(n << 3) + kp2 + 1];
                float c2 = c0, c3 = c1;
                mma8(c0, c1, c2, c3, ah0, ah1, wb.x);  // hi*hi
                mma8(c0, c1, c2, c3, al0, al1, wb.x);  // lo*hi
                mma8(c0, c1, c2, c3, ah0, ah1, wb.y);  // hi*lo
                c0 = tanh_f32(c0);
                c1 = tanh_f32(c1);
                c2 = tanh_f32(c2);
                c3 = tanh_f32(c3);
                h1p[rt][2 * n]     = pack_f16x2(c1, c0);  // row r0   (k even in low half)
                h1p[rt][2 * n + 1] = pack_f16x2(c3, c2);  // row r0+8
            }
        }

        // ================= Phase B: GEMM2 (h1 x splitW2) + tanh(f16x2) + GEMM3 (splitW3) ====
        float ea[2][4];
        #pragma unroll
        for (int rt = 0; rt < 2; ++rt) {
            ea[rt][0] = (kp == 0) ? b3v : 0.0f;
            ea[rt][1] = 0.0f;
            ea[rt][2] = ea[rt][0];
            ea[rt][3] = 0.0f;
        }

        #pragma unroll
        for (int p = 0; p < 4; ++p) {  // ntile pair (2p, 2p+1) == GEMM3 k-step p
            float c[2][8];
            #pragma unroll
            for (int rt = 0; rt < 2; ++rt) {
                c[rt][0] = b2s[(2 * p << 3) + kp2];
                c[rt][1] = b2s[(2 * p << 3) + kp2 + 1];
                c[rt][2] = c[rt][0];       c[rt][3] = c[rt][1];
                c[rt][4] = b2s[((2 * p + 1) << 3) + kp2];
                c[rt][5] = b2s[((2 * p + 1) << 3) + kp2 + 1];
                c[rt][6] = c[rt][4];       c[rt][7] = c[rt][5];
            }
            #pragma unroll
            for (int ks = 0; ks < 4; ++ks) {
                uint4 q0 = w2f[(ks * 8 + 2 * p) * 32 + lane];
                uint4 q1 = w2f[(ks * 8 + 2 * p + 1) * 32 + lane];
                #pragma unroll
                for (int rt = 0; rt < 2; ++rt) {
                    unsigned a0 = h1p[rt][4 * ks], a1 = h1p[rt][4 * ks + 1];
                    unsigned a2 = h1p[rt][4 * ks + 2], a3 = h1p[rt][4 * ks + 3];
                    mma16(c[rt][0], c[rt][1], c[rt][2], c[rt][3], a0, a1, a2, a3, q0.x, q0.y);
                    mma16(c[rt][0], c[rt][1], c[rt][2], c[rt][3], a0, a1, a2, a3, q0.z, q0.w);
                    mma16(c[rt][4], c[rt][5], c[rt][6], c[rt][7], a0, a1, a2, a3, q1.x, q1.y);
                    mma16(c[rt][4], c[rt][5], c[rt][6], c[rt][7], a0, a1, a2, a3, q1.z, q1.w);
                }
            }
            // tanh(h2) in f16x2; packed accs feed GEMM3 A-fragments directly
            uint4 q3 = w3f[p * 32 + lane];
            #pragma unroll
            for (int rt = 0; rt < 2; ++rt) {
                unsigned u0 = tanh_f16x2(pack_f16x2(c[rt][1], c[rt][0]));
                unsigned u1 = tanh_f16x2(pack_f16x2(c[rt][3], c[rt][2]));
                unsigned u2 = tanh_f16x2(pack_f16x2(c[rt][5], c[rt][4]));
                unsigned u3 = tanh_f16x2(pack_f16x2(c[rt][7], c[rt][6]));
                mma16(ea[rt][0], ea[rt][1], ea[rt][2], ea[rt][3], u0, u1, u2, u3, q3.x, q3.y);
                mma16(ea[rt][0], ea[rt][1], ea[rt][2], ea[rt][3], u0, u1, u2, u3, q3.z, q3.w);
            }
        }

        // ================= store e (col 0 of GEMM3 result lives in lanes with kp==0) =======
        if (kp == 0) {
            #pragma unroll
            for (int rt = 0; rt < 2; ++rt) {
                int r0 = sb + rt * 16 + row8;
                out[(size_t)r0 * ADIM + a]       = ea[rt][0];
                out[(size_t)(r0 + 8) * ADIM + a] = ea[rt][2];
            }
        }
    }
}

extern "C" void kernel_launch(void* const* d_in, const int* in_sizes, int n_in,
                              void* d_out, int out_size) {
    const float* g  = (const float*)d_in[0];
    const float* W1 = (const float*)d_in[1];
    const float* b1 = (const float*)d_in[2];
    const float* W2 = (const float*)d_in[3];
    const float* b2 = (const float*)d_in[4];
    const float* W3 = (const float*)d_in[5];
    const float* b3 = (const float*)d_in[6];
    float* out = (float*)d_out;

    dim3 grid(ADIM, 8);
    dim3 block(256);
    nn_grouped_mlp_kernel<<<grid, block>>>(g, W1, b1, W2, b2, W3, b3, out);
}

// round 8
// speedup vs baseline: 1.0352x; 1.0352x over previous
#include <cuda_runtime.h>
#include <cuda_fp16.h>
#include <stdint.h>

// Problem constants
#define SDIM 4096
#define ADIM 1024
#define DDIM 5
#define HDIM 64

// ---------------- low-level helpers ----------------

__device__ __forceinline__ float tanh_f32(float x) {
    float y;
    asm("tanh.approx.f32 %0, %1;" : "=f"(y) : "f"(x));
    return y;
}

__device__ __forceinline__ unsigned tanh_f16x2(unsigned x) {
    unsigned y;
    asm("tanh.approx.f16x2 %0, %1;" : "=r"(y) : "r"(x));
    return y;
}

// pack: result.lo = lo_val, result.hi = hi_val  (cvt.rn.f16x2.f32 d,a,b -> d.hi=a, d.lo=b)
__device__ __forceinline__ unsigned pack_f16x2(float hi_val, float lo_val) {
    unsigned d;
    asm("cvt.rn.f16x2.f32 %0, %1, %2;" : "=r"(d) : "f"(hi_val), "f"(lo_val));
    return d;
}

__device__ __forceinline__ unsigned pack_halves(__half lo, __half hi) {
    return ((unsigned)__half_as_ushort(hi) << 16) | (unsigned)__half_as_ushort(lo);
}

// fp16 two-term split of (x0,x1): hi = rn(x), lo = rn(x - f32(hi)); packed k-order (x0 in low half)
__device__ __forceinline__ void split2(float x0, float x1, unsigned& hi, unsigned& lo) {
    __half h0 = __float2half_rn(x0);
    __half h1 = __float2half_rn(x1);
    float r0 = x0 - __half2float(h0);
    float r1 = x1 - __half2float(h1);
    hi = pack_halves(h0, h1);
    lo = pack_halves(__float2half_rn(r0), __float2half_rn(r1));
}

__device__ __forceinline__ void mma16(float& c0, float& c1, float& c2, float& c3,
                                      unsigned a0, unsigned a1, unsigned a2, unsigned a3,
                                      unsigned b0, unsigned b1) {
    asm("mma.sync.aligned.m16n8k16.row.col.f32.f16.f16.f32 "
        "{%0,%1,%2,%3},{%4,%5,%6,%7},{%8,%9},{%0,%1,%2,%3};"
        : "+f"(c0), "+f"(c1), "+f"(c2), "+f"(c3)
        : "r"(a0), "r"(a1), "r"(a2), "r"(a3), "r"(b0), "r"(b1));
}

__device__ __forceinline__ void mma8(float& c0, float& c1, float& c2, float& c3,
                                     unsigned a0, unsigned a1, unsigned b0) {
    asm("mma.sync.aligned.m16n8k8.row.col.f32.f16.f16.f32 "
        "{%0,%1,%2,%3},{%4,%5},{%6},{%0,%1,%2,%3};"
        : "+f"(c0), "+f"(c1), "+f"(c2), "+f"(c3)
        : "r"(a0), "r"(a1), "r"(b0));
}

// ---------------- kernel ----------------
// Grid: (ADIM, 4). Block: 256 threads (8 warps), 2 blocks/SM.
// Block (a, y) handles atom a, rows [y*1024, y*1024+1024).
// Each warp processes 32 rows per iteration (2 row-tiles of 16), 4 iterations.

__global__ __launch_bounds__(256, 2)
void nn_grouped_mlp_kernel(const float* __restrict__ g,
                           const float* __restrict__ W1,
                           const float* __restrict__ b1,
                           const float* __restrict__ W2,
                           const float* __restrict__ b2,
                           const float* __restrict__ W3,
                           const float* __restrict__ b3,
                           float* __restrict__ out) {
    // smem: pre-swizzled B-fragments (fp16 hi/lo split) + biases
    __shared__ uint4 w2f[1024];  // [kstep(4)][ntile(8)][lane(32)] : {hi_b0,hi_b1,lo_b0,lo_b1}  16 KB
    __shared__ uint2 w1f[256];   // [ntile(8)][lane(32)]           : {hi_b0, lo_b0}             2 KB
    __shared__ uint4 w3f[128];   // [kstep(4)][lane(32)]           : {hi_b0,hi_b1,lo_b0,lo_b1}  2 KB
    __shared__ float b1s[HDIM];
    __shared__ float b2s[HDIM];

    const int a    = blockIdx.x;
    const int tid  = threadIdx.x;
    const int lane = tid & 31;
    const int warp = tid >> 5;
    const int kp   = lane & 3;   // k-pair index within fragments
    const int row8 = lane >> 2;  // row within 8-row group / n-col selector

    // ---- preprocess W2 into split B-fragments ----
    {
        const float* W2a = W2 + a * (HDIM * HDIM);
        #pragma unroll
        for (int c = tid; c < 1024; c += 256) {
            int l    = c & 31;
            int lkp  = l & 3;
            int colg = (((c >> 5) & 7) << 3) + (l >> 2);  // 8*ntile + lane/4
            int k0   = ((c >> 8) << 4) + (lkp << 1);      // 16*kstep + 2*kp
            float f0 = W2a[(k0    ) * HDIM + colg];
            float f1 = W2a[(k0 + 1) * HDIM + colg];
            float f2 = W2a[(k0 + 8) * HDIM + colg];
            float f3 = W2a[(k0 + 9) * HDIM + colg];
            uint4 q;
            split2(f0, f1, q.x, q.z);
            split2(f2, f3, q.y, q.w);
            w2f[c] = q;
        }
    }
    // ---- preprocess W1 (K padded 5 -> 8) ----
    if (tid < 256) {
        const float* W1a = W1 + a * (DDIM * HDIM);
        int l    = tid & 31;
        int lkp  = l & 3;
        int colg = ((tid >> 5) << 3) + (l >> 2);
        int k0 = 2 * lkp, k1 = 2 * lkp + 1;
        float f0 = (k0 < DDIM) ? W1a[k0 * HDIM + colg] : 0.0f;
        float f1 = (k1 < DDIM) ? W1a[k1 * HDIM + colg] : 0.0f;
        uint2 q;
        split2(f0, f1, q.x, q.y);
        w1f[tid] = q;
    }
    // ---- preprocess W3 (n=8 tile, only col 0 real) ----
    if (tid < 128) {
        const float* W3a = W3 + a * HDIM;
        int l    = tid & 31;
        int lkp  = l & 3;
        int colg = l >> 2;
        int k0   = ((tid >> 5) << 4) + (lkp << 1);
        float f0 = 0.f, f1 = 0.f, f2 = 0.f, f3 = 0.f;
        if (colg == 0) {
            f0 = W3a[k0];
            f1 = W3a[k0 + 1];
            f2 = W3a[k0 + 8];
            f3 = W3a[k0 + 9];
        }
        uint4 q;
        split2(f0, f1, q.x, q.z);
        split2(f2, f3, q.y, q.w);
        w3f[tid] = q;
    }
    // ---- biases into smem (frees 32 registers vs per-thread copies) ----
    if (tid < HDIM) {
        b1s[tid] = b1[a * HDIM + tid];
        b2s[tid] = b2[a * HDIM + tid];
    }
    const float b3v = b3[a];

    __syncthreads();

    const int sbase = blockIdx.y * 1024;
    const int kp2   = kp << 1;

    #pragma unroll
    for (int it = 0; it < 4; ++it) {
        const int sb = sbase + it * 256 + warp * 32;  // first row of this warp's 32-row chunk

        // ================= Phase A: GEMM1 (split fp16 MMA) + tanh(f32) + pack h1 ============
        // h1p[rt][4*ks + {0..3}] are directly the GEMM2 A-fragment registers.
        unsigned h1p[2][16];
        #pragma unroll
        for (int rt = 0; rt < 2; ++rt) {
            const int r0 = sb + rt * 16 + row8;  // rows r0 and r0+8
            const float* g0 = g + ((size_t)r0 * ADIM + a) * DDIM;
            const float* g1 = g0 + (size_t)8 * ADIM * DDIM;
            const int k0 = kp2, k1 = kp2 + 1;
            float x00 = (k0 < DDIM) ? g0[k0] : 0.0f;
            float x01 = (k1 < DDIM) ? g0[k1] : 0.0f;
            float x10 = (k0 < DDIM) ? g1[k0] : 0.0f;
            float x11 = (k1 < DDIM) ? g1[k1] : 0.0f;
            unsigned ah0, al0, ah1, al1;
            split2(x00, x01, ah0, al0);
            split2(x10, x11, ah1, al1);

            #pragma unroll
            for (int n = 0; n < 8; ++n) {
                uint2 wb = w1f[n * 32 + lane];
                float c0 = b1s[(n << 3) + kp2];
                float c1 = b1s[(n << 3) + kp2 + 1];
                float c2 = c0, c3 = c1;
                mma8(c0, c1, c2, c3, ah0, ah1, wb.x);  // hi*hi
                mma8(c0, c1, c2, c3, al0, al1, wb.x);  // lo*hi
                mma8(c0, c1, c2, c3, ah0, ah1, wb.y);  // hi*lo
                c0 = tanh_f32(c0);
                c1 = tanh_f32(c1);
                c2 = tanh_f32(c2);
                c3 = tanh_f32(c3);
                h1p[rt][2 * n]     = pack_f16x2(c1, c0);  // row r0   (k even in low half)
                h1p[rt][2 * n + 1] = pack_f16x2(c3, c2);  // row r0+8
            }
        }

        // ================= Phase B: GEMM2 (h1 x splitW2) + tanh(f16x2) + GEMM3 (splitW3) ====
        float ea[2][4];
        #pragma unroll
        for (int rt = 0; rt < 2; ++rt) {
            ea[rt][0] = (kp == 0) ? b3v : 0.0f;
            ea[rt][1] = 0.0f;
            ea[rt][2] = ea[rt][0];
            ea[rt][3] = 0.0f;
        }

        #pragma unroll
        for (int p = 0; p < 4; ++p) {  // ntile pair (2p, 2p+1) == GEMM3 k-step p
            float c[2][8];
            #pragma unroll
            for (int rt = 0; rt < 2; ++rt) {
                c[rt][0] = b2s[(2 * p << 3) + kp2];
                c[rt][1] = b2s[(2 * p << 3) + kp2 + 1];
                c[rt][2] = c[rt][0];       c[rt][3] = c[rt][1];
                c[rt][4] = b2s[((2 * p + 1) << 3) + kp2];
                c[rt][5] = b2s[((2 * p + 1) << 3) + kp2 + 1];
                c[rt][6] = c[rt][4];       c[rt][7] = c[rt][5];
            }
            #pragma unroll
            for (int ks = 0; ks < 4; ++ks) {
                uint4 q0 = w2f[(ks * 8 + 2 * p) * 32 + lane];
                uint4 q1 = w2f[(ks * 8 + 2 * p + 1) * 32 + lane];
                #pragma unroll
                for (int rt = 0; rt < 2; ++rt) {
                    unsigned a0 = h1p[rt][4 * ks], a1 = h1p[rt][4 * ks + 1];
                    unsigned a2 = h1p[rt][4 * ks + 2], a3 = h1p[rt][4 * ks + 3];
                    mma16(c[rt][0], c[rt][1], c[rt][2], c[rt][3], a0, a1, a2, a3, q0.x, q0.y);
                    mma16(c[rt][0], c[rt][1], c[rt][2], c[rt][3], a0, a1, a2, a3, q0.z, q0.w);
                    mma16(c[rt][4], c[rt][5], c[rt][6], c[rt][7], a0, a1, a2, a3, q1.x, q1.y);
                    mma16(c[rt][4], c[rt][5], c[rt][6], c[rt][7], a0, a1, a2, a3, q1.z, q1.w);
                }
            }
            // tanh(h2) in f16x2; packed accs feed GEMM3 A-fragments directly
            uint4 q3 = w3f[p * 32 + lane];
            #pragma unroll
            for (int rt = 0; rt < 2; ++rt) {
                unsigned u0 = tanh_f16x2(pack_f16x2(c[rt][1], c[rt][0]));
                unsigned u1 = tanh_f16x2(pack_f16x2(c[rt][3], c[rt][2]));
                unsigned u2 = tanh_f16x2(pack_f16x2(c[rt][5], c[rt][4]));
                unsigned u3 = tanh_f16x2(pack_f16x2(c[rt][7], c[rt][6]));
                mma16(ea[rt][0], ea[rt][1], ea[rt][2], ea[rt][3], u0, u1, u2, u3, q3.x, q3.y);
                mma16(ea[rt][0], ea[rt][1], ea[rt][2], ea[rt][3], u0, u1, u2, u3, q3.z, q3.w);
            }
        }

        // ================= store e (col 0 of GEMM3 result lives in lanes with kp==0) =======
        if (kp == 0) {
            #pragma unroll
            for (int rt = 0; rt < 2; ++rt) {
                int r0 = sb + rt * 16 + row8;
                out[(size_t)r0 * ADIM + a]       = ea[rt][0];
                out[(size_t)(r0 + 8) * ADIM + a] = ea[rt][2];
            }
        }
    }
}

extern "C" void kernel_launch(void* const* d_in, const int* in_sizes, int n_in,
                              void* d_out, int out_size) {
    const float* g  = (const float*)d_in[0];
    const float* W1 = (const float*)d_in[1];
    const float* b1 = (const float*)d_in[2];
    const float* W2 = (const float*)d_in[3];
    const float* b2 = (const float*)d_in[4];
    const float* W3 = (const float*)d_in[5];
    const float* b3 = (const float*)d_in[6];
    float* out = (float*)d_out;

    dim3 grid(ADIM, 4);
    dim3 block(256);
    nn_grouped_mlp_kernel<<<grid, block>>>(g, W1, b1, W2, b2, W3, b3, out);
}

// round 10
// speedup vs baseline: 1.3206x; 1.2757x over previous
#include <cuda_runtime.h>
#include <cuda_fp16.h>
#include <stdint.h>

// Problem constants
#define SDIM 4096
#define ADIM 1024
#define DDIM 5
#define HDIM 64

// ---------------- low-level helpers ----------------

__device__ __forceinline__ float tanh_f32(float x) {
    float y;
    asm("tanh.approx.f32 %0, %1;" : "=f"(y) : "f"(x));
    return y;
}

__device__ __forceinline__ unsigned tanh_f16x2(unsigned x) {
    unsigned y;
    asm("tanh.approx.f16x2 %0, %1;" : "=r"(y) : "r"(x));
    return y;
}

// pack: result.lo = lo_val, result.hi = hi_val  (cvt.rn.f16x2.f32 d,a,b -> d.hi=a, d.lo=b)
__device__ __forceinline__ unsigned pack_f16x2(float hi_val, float lo_val) {
    unsigned d;
    asm("cvt.rn.f16x2.f32 %0, %1, %2;" : "=r"(d) : "f"(hi_val), "f"(lo_val));
    return d;
}

__device__ __forceinline__ unsigned pack_halves(__half lo, __half hi) {
    return ((unsigned)__half_as_ushort(hi) << 16) | (unsigned)__half_as_ushort(lo);
}

// fp16 two-term split of (x0,x1): hi = rn(x), lo = rn(x - f32(hi)); packed k-order (x0 in low half)
__device__ __forceinline__ void split2(float x0, float x1, unsigned& hi, unsigned& lo) {
    __half h0 = __float2half_rn(x0);
    __half h1 = __float2half_rn(x1);
    float r0 = x0 - __half2float(h0);
    float r1 = x1 - __half2float(h1);
    hi = pack_halves(h0, h1);
    lo = pack_halves(__float2half_rn(r0), __float2half_rn(r1));
}

__device__ __forceinline__ void mma16(float& c0, float& c1, float& c2, float& c3,
                                      unsigned a0, unsigned a1, unsigned a2, unsigned a3,
                                      unsigned b0, unsigned b1) {
    asm("mma.sync.aligned.m16n8k16.row.col.f32.f16.f16.f32 "
        "{%0,%1,%2,%3},{%4,%5,%6,%7},{%8,%9},{%0,%1,%2,%3};"
        : "+f"(c0), "+f"(c1), "+f"(c2), "+f"(c3)
        : "r"(a0), "r"(a1), "r"(a2), "r"(a3), "r"(b0), "r"(b1));
}

__device__ __forceinline__ void mma8(float& c0, float& c1, float& c2, float& c3,
                                     unsigned a0, unsigned a1, unsigned b0) {
    asm("mma.sync.aligned.m16n8k8.row.col.f32.f16.f16.f32 "
        "{%0,%1,%2,%3},{%4,%5},{%6},{%0,%1,%2,%3};"
        : "+f"(c0), "+f"(c1), "+f"(c2), "+f"(c3)
        : "r"(a0), "r"(a1), "r"(b0));
}

// ---------------- kernel ----------------
// Grid: (ADIM, 4). Block: 256 threads (8 warps), 1 block/SM.
// Block (a, y) handles atom a, rows [y*1024, y*1024+1024).
// Each warp: 4 chunks of 32 rows, software-pipelined:
//   Phase A (GEMM1+tanh) of chunk i+1 is interleaved into Phase B (GEMM2/3) of chunk i
//   so MUFU/FMA/cvt work issues in the shadow of the HMMA bursts.

__global__ __launch_bounds__(256, 1)
void nn_grouped_mlp_kernel(const float* __restrict__ g,
                           const float* __restrict__ W1,
                           const float* __restrict__ b1,
                           const float* __restrict__ W2,
                           const float* __restrict__ b2,
                           const float* __restrict__ W3,
                           const float* __restrict__ b3,
                           float* __restrict__ out) {
    // smem: pre-swizzled B-fragments (fp16 hi/lo split) + biases
    __shared__ uint4 w2f[1024];  // [kstep(4)][ntile(8)][lane(32)] : {hi_b0,hi_b1,lo_b0,lo_b1}  16 KB
    __shared__ uint2 w1f[256];   // [ntile(8)][lane(32)]           : {hi_b0, lo_b0}             2 KB
    __shared__ uint4 w3f[128];   // [kstep(4)][lane(32)]           : {hi_b0,hi_b1,lo_b0,lo_b1}  2 KB
    __shared__ float b1s[HDIM];
    __shared__ float b2s[HDIM];

    const int a    = blockIdx.x;
    const int tid  = threadIdx.x;
    const int lane = tid & 31;
    const int warp = tid >> 5;
    const int kp   = lane & 3;   // k-pair index within fragments
    const int row8 = lane >> 2;  // row within 8-row group / n-col selector

    // ---- preprocess W2 into split B-fragments ----
    {
        const float* W2a = W2 + a * (HDIM * HDIM);
        #pragma unroll
        for (int c = tid; c < 1024; c += 256) {
            int l    = c & 31;
            int lkp  = l & 3;
            int colg = (((c >> 5) & 7) << 3) + (l >> 2);  // 8*ntile + lane/4
            int k0   = ((c >> 8) << 4) + (lkp << 1);      // 16*kstep + 2*kp
            float f0 = W2a[(k0    ) * HDIM + colg];
            float f1 = W2a[(k0 + 1) * HDIM + colg];
            float f2 = W2a[(k0 + 8) * HDIM + colg];
            float f3 = W2a[(k0 + 9) * HDIM + colg];
            uint4 q;
            split2(f0, f1, q.x, q.z);
            split2(f2, f3, q.y, q.w);
            w2f[c] = q;
        }
    }
    // ---- preprocess W1 (K padded 5 -> 8) ----
    if (tid < 256) {
        const float* W1a = W1 + a * (DDIM * HDIM);
        int l    = tid & 31;
        int lkp  = l & 3;
        int colg = ((tid >> 5) << 3) + (l >> 2);
        int k0 = 2 * lkp, k1 = 2 * lkp + 1;
        float f0 = (k0 < DDIM) ? W1a[k0 * HDIM + colg] : 0.0f;
        float f1 = (k1 < DDIM) ? W1a[k1 * HDIM + colg] : 0.0f;
        uint2 q;
        split2(f0, f1, q.x, q.y);
        w1f[tid] = q;
    }
    // ---- preprocess W3 (n=8 tile, only col 0 real) ----
    if (tid < 128) {
        const float* W3a = W3 + a * HDIM;
        int l    = tid & 31;
        int lkp  = l & 3;
        int colg = l >> 2;
        int k0   = ((tid >> 5) << 4) + (lkp << 1);
        float f0 = 0.f, f1 = 0.f, f2 = 0.f, f3 = 0.f;
        if (colg == 0) {
            f0 = W3a[k0];
            f1 = W3a[k0 + 1];
            f2 = W3a[k0 + 8];
            f3 = W3a[k0 + 9];
        }
        uint4 q;
        split2(f0, f1, q.x, q.z);
        split2(f2, f3, q.y, q.w);
        w3f[tid] = q;
    }
    // ---- biases into smem ----
    if (tid < HDIM) {
        b1s[tid] = b1[a * HDIM + tid];
        b2s[tid] = b2[a * HDIM + tid];
    }
    const float b3v = b3[a];

    __syncthreads();

    const int sbase = blockIdx.y * 1024 + warp * 32;
    const int kp2   = kp << 1;
    const bool k0ok = (kp2 < DDIM);
    const bool k1ok = (kp2 + 1 < DDIM);

    // ---- pipeline state ----
    float    graw[8];       // raw g for NEXT chunk: [rt*4 + {x00,x01,x10,x11}]
    unsigned gs[8];         // split g frags for chunk whose Phase A is in flight
    unsigned h1b0[2][16];   // double-buffered GEMM2 A-fragments, rt = 0
    unsigned h1b1[2][16];   // double-buffered GEMM2 A-fragments, rt = 1

    auto load_g = [&](int it) {
        #pragma unroll
        for (int rt = 0; rt < 2; ++rt) {
            const int r0 = sbase + it * 256 + rt * 16 + row8;
            const float* g0 = g + ((size_t)r0 * ADIM + a) * DDIM;
            const float* g1 = g0 + (size_t)8 * ADIM * DDIM;
            graw[4 * rt + 0] = k0ok ? g0[kp2]     : 0.0f;
            graw[4 * rt + 1] = k1ok ? g0[kp2 + 1] : 0.0f;
            graw[4 * rt + 2] = k0ok ? g1[kp2]     : 0.0f;
            graw[4 * rt + 3] = k1ok ? g1[kp2 + 1] : 0.0f;
        }
    };
    auto split_g = [&]() {
        #pragma unroll
        for (int rt = 0; rt < 2; ++rt) {
            split2(graw[4 * rt + 0], graw[4 * rt + 1], gs[4 * rt + 0], gs[4 * rt + 1]);
            split2(graw[4 * rt + 2], graw[4 * rt + 3], gs[4 * rt + 2], gs[4 * rt + 3]);
        }
    };
    // Phase A (GEMM1 + tanh + pack) for ntile pair (n0, n0+1), writing buffer `buf`.
    auto phaseA_pair = [&](int n0, int buf) {
        #pragma unroll
        for (int dn = 0; dn < 2; ++dn) {
            const int n = n0 + dn;
            uint2 wb = w1f[n * 32 + lane];
            {   // rt = 0
                float c0 = b1s[(n << 3) + kp2];
                float c1 = b1s[(n << 3) + kp2 + 1];
                float c2 = c0, c3 = c1;
                mma8(c0, c1, c2, c3, gs[0], gs[2], wb.x);  // hi*hi
                mma8(c0, c1, c2, c3, gs[1], gs[3], wb.x);  // lo*hi
                mma8(c0, c1, c2, c3, gs[0], gs[2], wb.y);  // hi*lo
                c0 = tanh_f32(c0); c1 = tanh_f32(c1);
                c2 = tanh_f32(c2); c3 = tanh_f32(c3);
                h1b0[buf][2 * n]     = pack_f16x2(c1, c0);  // row r0
                h1b0[buf][2 * n + 1] = pack_f16x2(c3, c2);  // row r0+8
            }
            {   // rt = 1
                float c0 = b1s[(n << 3) + kp2];
                float c1 = b1s[(n << 3) + kp2 + 1];
                float c2 = c0, c3 = c1;
                mma8(c0, c1, c2, c3, gs[4], gs[6], wb.x);
                mma8(c0, c1, c2, c3, gs[5], gs[7], wb.x);
                mma8(c0, c1, c2, c3, gs[4], gs[6], wb.y);
                c0 = tanh_f32(c0); c1 = tanh_f32(c1);
                c2 = tanh_f32(c2); c3 = tanh_f32(c3);
                h1b1[buf][2 * n]     = pack_f16x2(c1, c0);
                h1b1[buf][2 * n + 1] = pack_f16x2(c3, c2);
            }
        }
    };

    // ================= prologue: Phase A of chunk 0 =================
    load_g(0);
    split_g();
    #pragma unroll
    for (int p = 0; p < 4; ++p) phaseA_pair(2 * p, 0);

    // ================= pipelined main loop =================
    #pragma unroll
    for (int it = 0; it < 4; ++it) {
        const int cur = it & 1;
        const int nxt = cur ^ 1;

        if (it < 3) load_g(it + 1);  // LDG issued a full phase early

        float ea[2][4];
        #pragma unroll
        for (int rt = 0; rt < 2; ++rt) {
            ea[rt][0] = (kp == 0) ? b3v : 0.0f;
            ea[rt][1] = 0.0f;
            ea[rt][2] = ea[rt][0];
            ea[rt][3] = 0.0f;
        }

        #pragma unroll
        for (int p = 0; p < 4; ++p) {  // ntile pair (2p, 2p+1) == GEMM3 k-step p
            float c[2][8];
            #pragma unroll
            for (int rt = 0; rt < 2; ++rt) {
                c[rt][0] = b2s[(2 * p << 3) + kp2];
                c[rt][1] = b2s[(2 * p << 3) + kp2 + 1];
                c[rt][2] = c[rt][0];       c[rt][3] = c[rt][1];
                c[rt][4] = b2s[((2 * p + 1) << 3) + kp2];
                c[rt][5] = b2s[((2 * p + 1) << 3) + kp2 + 1];
                c[rt][6] = c[rt][4];       c[rt][7] = c[rt][5];
            }
            #pragma unroll
            for (int ks = 0; ks < 4; ++ks) {
                uint4 q0 = w2f[(ks * 8 + 2 * p) * 32 + lane];
                uint4 q1 = w2f[(ks * 8 + 2 * p + 1) * 32 + lane];
                {   // rt = 0
                    unsigned a0 = h1b0[cur][4 * ks],     a1 = h1b0[cur][4 * ks + 1];
                    unsigned a2 = h1b0[cur][4 * ks + 2], a3 = h1b0[cur][4 * ks + 3];
                    mma16(c[0][0], c[0][1], c[0][2], c[0][3], a0, a1, a2, a3, q0.x, q0.y);
                    mma16(c[0][0], c[0][1], c[0][2], c[0][3], a0, a1, a2, a3, q0.z, q0.w);
                    mma16(c[0][4], c[0][5], c[0][6], c[0][7], a0, a1, a2, a3, q1.x, q1.y);
                    mma16(c[0][4], c[0][5], c[0][6], c[0][7], a0, a1, a2, a3, q1.z, q1.w);
                }
                {   // rt = 1
                    unsigned a0 = h1b1[cur][4 * ks],     a1 = h1b1[cur][4 * ks + 1];
                    unsigned a2 = h1b1[cur][4 * ks + 2], a3 = h1b1[cur][4 * ks + 3];
                    mma16(c[1][0], c[1][1], c[1][2], c[1][3], a0, a1, a2, a3, q0.x, q0.y);
                    mma16(c[1][0], c[1][1], c[1][2], c[1][3], a0, a1, a2, a3, q0.z, q0.w);
                    mma16(c[1][4], c[1][5], c[1][6], c[1][7], a0, a1, a2, a3, q1.x, q1.y);
                    mma16(c[1][4], c[1][5], c[1][6], c[1][7], a0, a1, a2, a3, q1.z, q1.w);
                }
            }

            // interleave next chunk's Phase A (MUFU/FMA/cvt pipes) with this HMMA burst
            if (it < 3) {
                if (p == 0) split_g();
                phaseA_pair(2 * p, nxt);
            }

            // tanh(h2) in f16x2; packed accs feed GEMM3 A-fragments directly
            uint4 q3 = w3f[p * 32 + lane];
            #pragma unroll
            for (int rt = 0; rt < 2; ++rt) {
                unsigned u0 = tanh_f16x2(pack_f16x2(c[rt][1], c[rt][0]));
                unsigned u1 = tanh_f16x2(pack_f16x2(c[rt][3], c[rt][2]));
                unsigned u2 = tanh_f16x2(pack_f16x2(c[rt][5], c[rt][4]));
                unsigned u3 = tanh_f16x2(pack_f16x2(c[rt][7], c[rt][6]));
                mma16(ea[rt][0], ea[rt][1], ea[rt][2], ea[rt][3], u0, u1, u2, u3, q3.x, q3.y);
                mma16(ea[rt][0], ea[rt][1], ea[rt][2], ea[rt][3], u0, u1, u2, u3, q3.z, q3.w);
            }
        }

        // store e (col 0 of GEMM3 result lives in lanes with kp==0)
        if (kp == 0) {
            #pragma unroll
            for (int rt = 0; rt < 2; ++rt) {
                int r0 = sbase + it * 256 + rt * 16 + row8;
                out[(size_t)r0 * ADIM + a]       = ea[rt][0];
                out[(size_t)(r0 + 8) * ADIM + a] = ea[rt][2];
            }
        }
    }
}

extern "C" void kernel_launch(void* const* d_in, const int* in_sizes, int n_in,
                              void* d_out, int out_size) {
    const float* g  = (const float*)d_in[0];
    const float* W1 = (const float*)d_in[1];
    const float* b1 = (const float*)d_in[2];
    const float* W2 = (const float*)d_in[3];
    const float* b2 = (const float*)d_in[4];
    const float* W3 = (const float*)d_in[5];
    const float* b3 = (const float*)d_in[6];
    float* out = (float*)d_out;

    dim3 grid(ADIM, 4);
    dim3 block(256);
    nn_grouped_mlp_kernel<<<grid, block>>>(g, W1, b1, W2, b2, W3, b3, out);
}

// round 12
// speedup vs baseline: 1.8045x; 1.3665x over previous
#include <cuda_runtime.h>
#include <cuda_fp16.h>
#include <stdint.h>

// Problem constants
#define SDIM 4096
#define ADIM 1024
#define DDIM 5
#define HDIM 64

// ---------------- low-level helpers ----------------

__device__ __forceinline__ float tanh_f32(float x) {
    float y;
    asm("tanh.approx.f32 %0, %1;" : "=f"(y) : "f"(x));
    return y;
}

__device__ __forceinline__ unsigned tanh_f16x2(unsigned x) {
    unsigned y;
    asm("tanh.approx.f16x2 %0, %1;" : "=r"(y) : "r"(x));
    return y;
}

// pack: result.lo = lo_val, result.hi = hi_val  (cvt.rn.f16x2.f32 d,a,b -> d.hi=a, d.lo=b)
__device__ __forceinline__ unsigned pack_f16x2(float hi_val, float lo_val) {
    unsigned d;
    asm("cvt.rn.f16x2.f32 %0, %1, %2;" : "=r"(d) : "f"(hi_val), "f"(lo_val));
    return d;
}

__device__ __forceinline__ unsigned pack_halves(__half lo, __half hi) {
    return ((unsigned)__half_as_ushort(hi) << 16) | (unsigned)__half_as_ushort(lo);
}

// fp16 two-term split of (x0,x1): hi = rn(x), lo = rn(x - f32(hi)); packed k-order (x0 in low half)
__device__ __forceinline__ void split2(float x0, float x1, unsigned& hi, unsigned& lo) {
    __half h0 = __float2half_rn(x0);
    __half h1 = __float2half_rn(x1);
    float r0 = x0 - __half2float(h0);
    float r1 = x1 - __half2float(h1);
    hi = pack_halves(h0, h1);
    lo = pack_halves(__float2half_rn(r0), __float2half_rn(r1));
}

__device__ __forceinline__ void mma16(float& c0, float& c1, float& c2, float& c3,
                                      unsigned a0, unsigned a1, unsigned a2, unsigned a3,
                                      unsigned b0, unsigned b1) {
    asm("mma.sync.aligned.m16n8k16.row.col.f32.f16.f16.f32 "
        "{%0,%1,%2,%3},{%4,%5,%6,%7},{%8,%9},{%0,%1,%2,%3};"
        : "+f"(c0), "+f"(c1), "+f"(c2), "+f"(c3)
        : "r"(a0), "r"(a1), "r"(a2), "r"(a3), "r"(b0), "r"(b1));
}

__device__ __forceinline__ void mma8(float& c0, float& c1, float& c2, float& c3,
                                     unsigned a0, unsigned a1, unsigned b0) {
    asm("mma.sync.aligned.m16n8k8.row.col.f32.f16.f16.f32 "
        "{%0,%1,%2,%3},{%4,%5},{%6},{%0,%1,%2,%3};"
        : "+f"(c0), "+f"(c1), "+f"(c2), "+f"(c3)
        : "r"(a0), "r"(a1), "r"(b0));
}

// ---------------- kernel ----------------
// Grid: (ADIM, 4). Block: 256 threads (8 warps), 1 block/SM.
// Block (a, y) handles atom a, rows [y*1024, y*1024+1024).
// Each warp: 4 chunks of 32 rows, software-pipelined:
//   Phase A (GEMM1+tanh) of chunk i+1 is interleaved into Phase B (GEMM2/3) of chunk i.
// W2 is plain fp16 (no lo-correction): halves GEMM2 HMMA work + w2f LDS traffic.
// W1 keeps the full 3-term split (cheap, and its error amplifies more).

__global__ __launch_bounds__(256, 1)
void nn_grouped_mlp_kernel(const float* __restrict__ g,
                           const float* __restrict__ W1,
                           const float* __restrict__ b1,
                           const float* __restrict__ W2,
                           const float* __restrict__ b2,
                           const float* __restrict__ W3,
                           const float* __restrict__ b3,
                           float* __restrict__ out) {
    // smem: pre-swizzled B-fragments + biases
    __shared__ uint2 w2f[1024];  // [kstep(4)][ntile(8)][lane(32)] : {hi_b0, hi_b1}  8 KB
    __shared__ uint2 w1f[256];   // [ntile(8)][lane(32)]           : {hi_b0, lo_b0}  2 KB
    __shared__ uint4 w3f[128];   // [kstep(4)][lane(32)]           : {hi_b0,hi_b1,lo_b0,lo_b1}  2 KB
    __shared__ float b1s[HDIM];
    __shared__ float b2s[HDIM];

    const int a    = blockIdx.x;
    const int tid  = threadIdx.x;
    const int lane = tid & 31;
    const int warp = tid >> 5;
    const int kp   = lane & 3;   // k-pair index within fragments
    const int row8 = lane >> 2;  // row within 8-row group / n-col selector

    // ---- preprocess W2 into fp16 B-fragments (hi only) ----
    {
        const float* W2a = W2 + a * (HDIM * HDIM);
        #pragma unroll
        for (int c = tid; c < 1024; c += 256) {
            int l    = c & 31;
            int lkp  = l & 3;
            int colg = (((c >> 5) & 7) << 3) + (l >> 2);  // 8*ntile + lane/4
            int k0   = ((c >> 8) << 4) + (lkp << 1);      // 16*kstep + 2*kp
            float f0 = W2a[(k0    ) * HDIM + colg];
            float f1 = W2a[(k0 + 1) * HDIM + colg];
            float f2 = W2a[(k0 + 8) * HDIM + colg];
            float f3 = W2a[(k0 + 9) * HDIM + colg];
            uint2 q;
            q.x = pack_halves(__float2half_rn(f0), __float2half_rn(f1));
            q.y = pack_halves(__float2half_rn(f2), __float2half_rn(f3));
            w2f[c] = q;
        }
    }
    // ---- preprocess W1 (K padded 5 -> 8), full hi/lo split ----
    if (tid < 256) {
        const float* W1a = W1 + a * (DDIM * HDIM);
        int l    = tid & 31;
        int lkp  = l & 3;
        int colg = ((tid >> 5) << 3) + (l >> 2);
        int k0 = 2 * lkp, k1 = 2 * lkp + 1;
        float f0 = (k0 < DDIM) ? W1a[k0 * HDIM + colg] : 0.0f;
        float f1 = (k1 < DDIM) ? W1a[k1 * HDIM + colg] : 0.0f;
        uint2 q;
        split2(f0, f1, q.x, q.y);
        w1f[tid] = q;
    }
    // ---- preprocess W3 (n=8 tile, only col 0 real), full hi/lo split ----
    if (tid < 128) {
        const float* W3a = W3 + a * HDIM;
        int l    = tid & 31;
        int lkp  = l & 3;
        int colg = l >> 2;
        int k0   = ((tid >> 5) << 4) + (lkp << 1);
        float f0 = 0.f, f1 = 0.f, f2 = 0.f, f3 = 0.f;
        if (colg == 0) {
            f0 = W3a[k0];
            f1 = W3a[k0 + 1];
            f2 = W3a[k0 + 8];
            f3 = W3a[k0 + 9];
        }
        uint4 q;
        split2(f0, f1, q.x, q.z);
        split2(f2, f3, q.y, q.w);
        w3f[tid] = q;
    }
    // ---- biases into smem ----
    if (tid < HDIM) {
        b1s[tid] = b1[a * HDIM + tid];
        b2s[tid] = b2[a * HDIM + tid];
    }
    const float b3v = b3[a];

    __syncthreads();

    const int sbase = blockIdx.y * 1024 + warp * 32;
    const int kp2   = kp << 1;
    const bool k0ok = (kp2 < DDIM);
    const bool k1ok = (kp2 + 1 < DDIM);

    // ---- pipeline state ----
    float    graw[8];       // raw g for NEXT chunk: [rt*4 + {x00,x01,x10,x11}]
    unsigned gs[8];         // split g frags for chunk whose Phase A is in flight
    unsigned h1b0[2][16];   // double-buffered GEMM2 A-fragments, rt = 0
    unsigned h1b1[2][16];   // double-buffered GEMM2 A-fragments, rt = 1

    auto load_g = [&](int it) {
        #pragma unroll
        for (int rt = 0; rt < 2; ++rt) {
            const int r0 = sbase + it * 256 + rt * 16 + row8;
            const float* g0 = g + ((size_t)r0 * ADIM + a) * DDIM;
            const float* g1 = g0 + (size_t)8 * ADIM * DDIM;
            graw[4 * rt + 0] = k0ok ? g0[kp2]     : 0.0f;
            graw[4 * rt + 1] = k1ok ? g0[kp2 + 1] : 0.0f;
            graw[4 * rt + 2] = k0ok ? g1[kp2]     : 0.0f;
            graw[4 * rt + 3] = k1ok ? g1[kp2 + 1] : 0.0f;
        }
    };
    auto split_g = [&]() {
        #pragma unroll
        for (int rt = 0; rt < 2; ++rt) {
            split2(graw[4 * rt + 0], graw[4 * rt + 1], gs[4 * rt + 0], gs[4 * rt + 1]);
            split2(graw[4 * rt + 2], graw[4 * rt + 3], gs[4 * rt + 2], gs[4 * rt + 3]);
        }
    };
    // Phase A (GEMM1 + tanh + pack) for ntile pair (n0, n0+1), writing buffer `buf`.
    auto phaseA_pair = [&](int n0, int buf) {
        #pragma unroll
        for (int dn = 0; dn < 2; ++dn) {
            const int n = n0 + dn;
            uint2 wb = w1f[n * 32 + lane];
            {   // rt = 0
                float c0 = b1s[(n << 3) + kp2];
                float c1 = b1s[(n << 3) + kp2 + 1];
                float c2 = c0, c3 = c1;
                mma8(c0, c1, c2, c3, gs[0], gs[2], wb.x);  // hi*hi
                mma8(c0, c1, c2, c3, gs[1], gs[3], wb.x);  // lo*hi
                mma8(c0, c1, c2, c3, gs[0], gs[2], wb.y);  // hi*lo
                c0 = tanh_f32(c0); c1 = tanh_f32(c1);
                c2 = tanh_f32(c2); c3 = tanh_f32(c3);
                h1b0[buf][2 * n]     = pack_f16x2(c1, c0);  // row r0
                h1b0[buf][2 * n + 1] = pack_f16x2(c3, c2);  // row r0+8
            }
            {   // rt = 1
                float c0 = b1s[(n << 3) + kp2];
                float c1 = b1s[(n << 3) + kp2 + 1];
                float c2 = c0, c3 = c1;
                mma8(c0, c1, c2, c3, gs[4], gs[6], wb.x);
                mma8(c0, c1, c2, c3, gs[5], gs[7], wb.x);
                mma8(c0, c1, c2, c3, gs[4], gs[6], wb.y);
                c0 = tanh_f32(c0); c1 = tanh_f32(c1);
                c2 = tanh_f32(c2); c3 = tanh_f32(c3);
                h1b1[buf][2 * n]     = pack_f16x2(c1, c0);
                h1b1[buf][2 * n + 1] = pack_f16x2(c3, c2);
            }
        }
    };

    // ================= prologue: Phase A of chunk 0 =================
    load_g(0);
    split_g();
    #pragma unroll
    for (int p = 0; p < 4; ++p) phaseA_pair(2 * p, 0);

    // ================= pipelined main loop =================
    #pragma unroll
    for (int it = 0; it < 4; ++it) {
        const int cur = it & 1;
        const int nxt = cur ^ 1;

        if (it < 3) load_g(it + 1);  // LDG issued a full phase early

        float ea[2][4];
        #pragma unroll
        for (int rt = 0; rt < 2; ++rt) {
            ea[rt][0] = (kp == 0) ? b3v : 0.0f;
            ea[rt][1] = 0.0f;
            ea[rt][2] = ea[rt][0];
            ea[rt][3] = 0.0f;
        }

        #pragma unroll
        for (int p = 0; p < 4; ++p) {  // ntile pair (2p, 2p+1) == GEMM3 k-step p
            float c[2][8];
            #pragma unroll
            for (int rt = 0; rt < 2; ++rt) {
                c[rt][0] = b2s[(2 * p << 3) + kp2];
                c[rt][1] = b2s[(2 * p << 3) + kp2 + 1];
                c[rt][2] = c[rt][0];       c[rt][3] = c[rt][1];
                c[rt][4] = b2s[((2 * p + 1) << 3) + kp2];
                c[rt][5] = b2s[((2 * p + 1) << 3) + kp2 + 1];
                c[rt][6] = c[rt][4];       c[rt][7] = c[rt][5];
            }
            #pragma unroll
            for (int ks = 0; ks < 4; ++ks) {
                uint2 q0 = w2f[(ks * 8 + 2 * p) * 32 + lane];
                uint2 q1 = w2f[(ks * 8 + 2 * p + 1) * 32 + lane];
                {   // rt = 0
                    unsigned a0 = h1b0[cur][4 * ks],     a1 = h1b0[cur][4 * ks + 1];
                    unsigned a2 = h1b0[cur][4 * ks + 2], a3 = h1b0[cur][4 * ks + 3];
                    mma16(c[0][0], c[0][1], c[0][2], c[0][3], a0, a1, a2, a3, q0.x, q0.y);
                    mma16(c[0][4], c[0][5], c[0][6], c[0][7], a0, a1, a2, a3, q1.x, q1.y);
                }
                {   // rt = 1
                    unsigned a0 = h1b1[cur][4 * ks],     a1 = h1b1[cur][4 * ks + 1];
                    unsigned a2 = h1b1[cur][4 * ks + 2], a3 = h1b1[cur][4 * ks + 3];
                    mma16(c[1][0], c[1][1], c[1][2], c[1][3], a0, a1, a2, a3, q0.x, q0.y);
                    mma16(c[1][4], c[1][5], c[1][6], c[1][7], a0, a1, a2, a3, q1.x, q1.y);
                }
            }

            // interleave next chunk's Phase A (MUFU/FMA/cvt pipes) with this HMMA burst
            if (it < 3) {
                if (p == 0) split_g();
                phaseA_pair(2 * p, nxt);
            }

            // tanh(h2) in f16x2; packed accs feed GEMM3 A-fragments directly
            uint4 q3 = w3f[p * 32 + lane];
            #pragma unroll
            for (int rt = 0; rt < 2; ++rt) {
                unsigned u0 = tanh_f16x2(pack_f16x2(c[rt][1], c[rt][0]));
                unsigned u1 = tanh_f16x2(pack_f16x2(c[rt][3], c[rt][2]));
                unsigned u2 = tanh_f16x2(pack_f16x2(c[rt][5], c[rt][4]));
                unsigned u3 = tanh_f16x2(pack_f16x2(c[rt][7], c[rt][6]));
                mma16(ea[rt][0], ea[rt][1], ea[rt][2], ea[rt][3], u0, u1, u2, u3, q3.x, q3.y);
                mma16(ea[rt][0], ea[rt][1], ea[rt][2], ea[rt][3], u0, u1, u2, u3, q3.z, q3.w);
            }
        }

        // store e (col 0 of GEMM3 result lives in lanes with kp==0)
        if (kp == 0) {
            #pragma unroll
            for (int rt = 0; rt < 2; ++rt) {
                int r0 = sbase + it * 256 + rt * 16 + row8;
                out[(size_t)r0 * ADIM + a]       = ea[rt][0];
                out[(size_t)(r0 + 8) * ADIM + a] = ea[rt][2];
            }
        }
    }
}

extern "C" void kernel_launch(void* const* d_in, const int* in_sizes, int n_in,
                              void* d_out, int out_size) {
    const float* g  = (const float*)d_in[0];
    const float* W1 = (const float*)d_in[1];
    const float* b1 = (const float*)d_in[2];
    const float* W2 = (const float*)d_in[3];
    const float* b2 = (const float*)d_in[4];
    const float* W3 = (const float*)d_in[5];
    const float* b3 = (const float*)d_in[6];
    float* out = (float*)d_out;

    dim3 grid(ADIM, 4);
    dim3 block(256);
    nn_grouped_mlp_kernel<<<grid, block>>>(g, W1, b1, W2, b2, W3, b3, out);
}